// round 1
// baseline (speedup 1.0000x reference)
#include <cuda_runtime.h>
#include <cuda_bf16.h>
#include <cstdint>

#define HID    96
#define HP1    97           // HID+1
#define PF     912673       // 97^3
#define R_TOTAL (HP1*HP1)   // 9409  (r = i*97 + j)
#define BSZ    64

#define TILE_R 96
#define TILES_PER_CTA 2
#define NCHUNK 50           // 50 * 2 * 96 = 9600 >= 9409
#define THREADS 192
#define RG 12               // r-groups (tid % 12)
#define TR 8                // r per thread  -> 12*8 = 96 rows
#define TB 4                // b per thread  -> 16*4 = 64 batches
#define KP 49               // k-pairs (98/2), pair 48 uses zero-padded lane 97

// Scratch (__device__ globals: no allocation, graph-safe)
__device__ __align__(16) float g_TT[HP1 * BSZ];      // [i][b] text_ext^T
__device__ __align__(16) float g_AT[HP1 * BSZ];      // [j][b] audio_ext^T
__device__ __align__(16) float g_VB[BSZ * 98];       // [b][k] video_ext, padded to 98, k=97 -> 0
__device__ float g_part[(size_t)NCHUNK * BSZ * HID]; // per-chunk partial h1

__global__ void setup_kernel(const float* __restrict__ text,
                             const float* __restrict__ audio,
                             const float* __restrict__ video) {
    int tid = blockIdx.x * blockDim.x + threadIdx.x;
    int nt  = gridDim.x * blockDim.x;
    for (int idx = tid; idx < HP1 * BSZ; idx += nt) {
        int i = idx / BSZ;
        int b = idx - i * BSZ;
        g_TT[idx] = (i == 0) ? 1.f : text [b * HID + i - 1];
        g_AT[idx] = (i == 0) ? 1.f : audio[b * HID + i - 1];
    }
    for (int idx = tid; idx < BSZ * 98; idx += nt) {
        int b = idx / 98;
        int k = idx - b * 98;
        float v = 0.f;
        if (k == 0)        v = 1.f;
        else if (k < HP1)  v = video[b * HID + k - 1];
        g_VB[idx] = v;
    }
}

// One CTA: output channel o (blockIdx.x), r-chunk (blockIdx.y).
// For each 96-row tile of W1[o]: stage to smem, GEMM over k with packed
// f32x2 FMAs (pair dim = k), fold t[b,i]*a[b,j] per row, accumulate hp[b].
__global__ __launch_bounds__(THREADS, 3)
void fusion_kernel(const float* __restrict__ W1) {
    __shared__ float Wsm[TILE_R * 98];   // row-padded to 98 floats (8B-aligned pairs)

    const int tid   = threadIdx.x;
    const int o     = blockIdx.x;
    const int chunk = blockIdx.y;
    const int rg    = tid % RG;          // r-group
    const int bg    = tid / RG;          // b-group, [0,16)
    const float* Wo = W1 + (size_t)o * PF;

    // zero padded k-lane (lane 97): guarantees 0 * 0 in pair 48 (no NaN from garbage)
    if (tid < TILE_R) Wsm[tid * 98 + 97] = 0.f;

    float hp[TB];
#pragma unroll
    for (int bb = 0; bb < TB; ++bb) hp[bb] = 0.f;

    // v_ext rows for this thread's 4 batches, as 64-bit k-pairs (49 per row)
    const unsigned long long* vb =
        reinterpret_cast<const unsigned long long*>(g_VB) + (size_t)(bg * TB) * 49;

    for (int t = 0; t < TILES_PER_CTA; ++t) {
        const int R0 = (chunk * TILES_PER_CTA + t) * TILE_R;
        if (R0 >= R_TOTAL) break;                 // uniform across block

        __syncthreads();
        // stage tile: contiguous, coalesced global read; pad rows beyond R_TOTAL with 0
        for (int idx = tid; idx < TILE_R * HP1; idx += THREADS) {
            int rloc = idx / HP1;
            int k    = idx - rloc * HP1;
            int r    = R0 + rloc;
            Wsm[rloc * 98 + k] = (r < R_TOTAL) ? Wo[(size_t)r * HP1 + k] : 0.f;
        }
        __syncthreads();

        unsigned long long acc[TR][TB];
#pragma unroll
        for (int rr = 0; rr < TR; ++rr)
#pragma unroll
            for (int bb = 0; bb < TB; ++bb) acc[rr][bb] = 0ull;

#pragma unroll 7
        for (int kp = 0; kp < KP; ++kp) {
            unsigned long long w2[TR], v2[TB];
#pragma unroll
            for (int rr = 0; rr < TR; ++rr)
                w2[rr] = *reinterpret_cast<const unsigned long long*>(
                             &Wsm[(rg + RG * rr) * 98 + 2 * kp]);
#pragma unroll
            for (int bb = 0; bb < TB; ++bb)
                v2[bb] = __ldg(&vb[(size_t)bb * 49 + kp]);
#pragma unroll
            for (int rr = 0; rr < TR; ++rr)
#pragma unroll
                for (int bb = 0; bb < TB; ++bb)
                    asm("fma.rn.f32x2 %0, %1, %2, %0;"
                        : "+l"(acc[rr][bb])
                        : "l"(w2[rr]), "l"(v2[bb]));
        }

        // fold: hp[b] += (acc.even + acc.odd) * t[b,i] * a[b,j]
#pragma unroll
        for (int rr = 0; rr < TR; ++rr) {
            int r = R0 + rg + RG * rr;
            if (r < R_TOTAL) {
                int i = r / HP1;
                int j = r - i * HP1;
                const float4 t4 = *reinterpret_cast<const float4*>(&g_TT[i * BSZ + bg * TB]);
                const float4 a4 = *reinterpret_cast<const float4*>(&g_AT[j * BSZ + bg * TB]);
                float tv[TB] = {t4.x, t4.y, t4.z, t4.w};
                float av[TB] = {a4.x, a4.y, a4.z, a4.w};
#pragma unroll
                for (int bb = 0; bb < TB; ++bb) {
                    unsigned long long a_ = acc[rr][bb];
                    float lo = __uint_as_float((unsigned)(a_ & 0xffffffffu));
                    float hi = __uint_as_float((unsigned)(a_ >> 32));
                    hp[bb] += (lo + hi) * (tv[bb] * av[bb]);
                }
            }
        }
    }

    // deterministic intra-CTA reduction across the 12 r-groups (reuse smem)
    __syncthreads();
    float* red = Wsm;
#pragma unroll
    for (int bb = 0; bb < TB; ++bb) red[tid * TB + bb] = hp[bb];
    __syncthreads();
    if (rg == 0) {
#pragma unroll
        for (int bb = 0; bb < TB; ++bb) {
            float s = 0.f;
#pragma unroll
            for (int g = 0; g < RG; ++g) s += red[(g + RG * bg) * TB + bb];
            int b = bg * TB + bb;
            g_part[((size_t)chunk * BSZ + b) * HID + o] = s;
        }
    }
}

// Sum chunk partials, then the tiny 96 -> 48 -> 3 MLP. One block per batch row.
__global__ void tail_kernel(const float* __restrict__ b1,
                            const float* __restrict__ W2,
                            const float* __restrict__ b2,
                            const float* __restrict__ W3,
                            const float* __restrict__ b3,
                            float* __restrict__ out) {
    __shared__ float h[HID];
    __shared__ float h2[HID / 2];
    const int b   = blockIdx.x;
    const int tid = threadIdx.x;

    if (tid < HID) {
        float s = b1[tid];
        for (int c = 0; c < NCHUNK; ++c)
            s += g_part[((size_t)c * BSZ + b) * HID + tid];
        h[tid] = fmaxf(s, 0.f);
    }
    __syncthreads();
    if (tid < HID / 2) {
        float s = b2[tid];
#pragma unroll 4
        for (int oo = 0; oo < HID; ++oo) s += h[oo] * W2[tid * HID + oo];
        h2[tid] = fmaxf(s, 0.f);
    }
    __syncthreads();
    if (tid < 3) {
        float s = b3[tid];
#pragma unroll
        for (int q = 0; q < HID / 2; ++q) s += h2[q] * W3[tid * (HID / 2) + q];
        out[b * 3 + tid] = s;
    }
}

extern "C" void kernel_launch(void* const* d_in, const int* in_sizes, int n_in,
                              void* d_out, int out_size) {
    const float* text  = (const float*)d_in[0];
    const float* audio = (const float*)d_in[1];
    const float* video = (const float*)d_in[2];
    const float* W1    = (const float*)d_in[3];
    const float* b1    = (const float*)d_in[4];
    const float* W2    = (const float*)d_in[5];
    const float* b2    = (const float*)d_in[6];
    const float* W3    = (const float*)d_in[7];
    const float* b3    = (const float*)d_in[8];
    float* out = (float*)d_out;

    setup_kernel<<<16, 256>>>(text, audio, video);
    fusion_kernel<<<dim3(HID, NCHUNK), THREADS>>>(W1);
    tail_kernel<<<BSZ, 96>>>(b1, W2, b2, W3, b3, out);
}